// round 17
// baseline (speedup 1.0000x reference)
#include <cuda_runtime.h>
#include <cstdint>
#include <mma.h>

using namespace nvcuda;

// Problem-shape constants (fixed for this dataset)
#define NMAX  65536
#define MKF   16384            // known points
#define C1    128
#define C2    256
#define CIN   384
#define COUT  256
#define NN_TILE 512
#define NSPLIT 8               // per-batch known-axis splits for three_nn
#define PARTS 512              // max row-blocks (N/128)
#define STATB2 256             // col_stats blocks for layer 2

// ---------------- scratch (device globals; no allocation allowed) ----------
__device__ float g_w[NMAX * 3];
__device__ int   g_i[NMAX * 3];
__device__ float g_ps[NSPLIT * NMAX * 3];
__device__ int   g_pi[NSPLIT * NMAX * 3];
__device__ float g_G [MKF  * COUT];      // G = kf @ W1a^T (16 MB, L2-resident)
__device__ float g_H [NMAX * COUT];      // layer-1 pre-BN output
__device__ float g_H2[NMAX * COUT];      // layer-2 pre-BN output
__device__ float g_psum[COUT * PARTS];   // [col][rowblock]
__device__ float g_psq [COUT * PARTS];
__device__ float g_scale[COUT];
__device__ float g_shift[COUT];

__device__ __forceinline__ float tf32_rnd(float x) {
    uint32_t u;
    asm("cvt.rna.tf32.f32 %0, %1;" : "=r"(u) : "f"(x));
    return __uint_as_float(u);
}

// ---------------- 1a) 3-NN partial pass (2 pts/thread, 8-way per-batch split)
__global__ __launch_bounds__(256) void three_nn_part(
    const float* __restrict__ unknown,
    const int*   __restrict__ ub_cnt,
    const float* __restrict__ known,
    const int*   __restrict__ kb_cnt,
    int N, int B)
{
    __shared__ float4 sk[NN_TILE];

    const int tid  = threadIdx.x;
    const int s    = blockIdx.y;
    const int base = blockIdx.x * 512;
    const int n0 = base + tid;
    const int n1 = base + 256 + tid;

    float ux0 = 0.f, uy0 = 0.f, uz0 = 0.f;
    float ux1 = 0.f, uy1 = 0.f, uz1 = 0.f;
    int b0i = -1, b1i = -1;
    if (n0 < N) { ux0 = unknown[n0*3]; uy0 = unknown[n0*3+1]; uz0 = unknown[n0*3+2]; }
    if (n1 < N) { ux1 = unknown[n1*3]; uy1 = unknown[n1*3+1]; uz1 = unknown[n1*3+2]; }
    {
        int acc = 0;
        for (int b = 0; b < B; b++) {
            int nx = acc + ub_cnt[b];
            if (n0 < N && n0 >= acc && n0 < nx) b0i = b;
            if (n1 < N && n1 >= acc && n1 < nx) b1i = b;
            acc = nx;
        }
    }

    const float NEG = -__int_as_float(0x7f800000);
    float s00 = NEG, s01 = NEG, s02 = NEG;
    float s10 = NEG, s11 = NEG, s12 = NEG;
    int   a00 = 0, a01 = 0, a02 = 0;
    int   a10 = 0, a11 = 0, a12 = 0;

    int kacc = 0;
    for (int b = 0; b < B; b++) {
        int ks = kacc;
        kacc += kb_cnt[b];
        int ke = kacc;
        bool act0 = (b0i == b), act1 = (b1i == b);

        int tloc = 0;
        for (int t = ks; t < ke; t += NN_TILE, tloc++) {
            if ((tloc & (NSPLIT - 1)) != s) continue;
            int any = __syncthreads_or((int)(act0 || act1));
            if (!any) continue;

            int cnt = min(NN_TILE, ke - t);
            __syncthreads();
            for (int i = tid; i < cnt; i += 256) {
                float kx = known[(t + i) * 3 + 0];
                float ky = known[(t + i) * 3 + 1];
                float kz = known[(t + i) * 3 + 2];
                float h  = 0.5f * (kx * kx + ky * ky + kz * kz);
                sk[i] = make_float4(kx, ky, kz, h);
            }
            __syncthreads();

#pragma unroll 4
            for (int j = 0; j < cnt; j++) {
                float4 kk = sk[j];
                int gi = t + j;
                float t0 = fmaf(ux0, kk.x, fmaf(uy0, kk.y, fmaf(uz0, kk.z, -kk.w)));
                float t1 = fmaf(ux1, kk.x, fmaf(uy1, kk.y, fmaf(uz1, kk.z, -kk.w)));
                t0 = act0 ? t0 : NEG;
                t1 = act1 ? t1 : NEG;
                if (t0 > s02) {
                    if (t0 > s01) {
                        s02 = s01; a02 = a01;
                        if (t0 > s00) { s01 = s00; a01 = a00; s00 = t0; a00 = gi; }
                        else          { s01 = t0;  a01 = gi; }
                    } else { s02 = t0; a02 = gi; }
                }
                if (t1 > s12) {
                    if (t1 > s11) {
                        s12 = s11; a12 = a11;
                        if (t1 > s10) { s11 = s10; a11 = a10; s10 = t1; a10 = gi; }
                        else          { s11 = t1;  a11 = gi; }
                    } else { s12 = t1; a12 = gi; }
                }
            }
        }
    }

    if (n0 < N) {
        size_t o = ((size_t)s * N + n0) * 3;
        g_ps[o+0] = s00; g_ps[o+1] = s01; g_ps[o+2] = s02;
        g_pi[o+0] = a00; g_pi[o+1] = a01; g_pi[o+2] = a02;
    }
    if (n1 < N) {
        size_t o = ((size_t)s * N + n1) * 3;
        g_ps[o+0] = s10; g_ps[o+1] = s11; g_ps[o+2] = s12;
        g_pi[o+0] = a10; g_pi[o+1] = a11; g_pi[o+2] = a12;
    }
}

// ---------------- 1b) merge partials -> weights + indices -------------------
__global__ void three_nn_merge(const float* __restrict__ unknown,
                               const float* __restrict__ known,
                               int N)
{
    int n = blockIdx.x * blockDim.x + threadIdx.x;
    if (n >= N) return;

    float cs[NSPLIT * 3];
    int   ci[NSPLIT * 3];
#pragma unroll
    for (int s = 0; s < NSPLIT; s++) {
        size_t o = ((size_t)s * N + n) * 3;
#pragma unroll
        for (int q = 0; q < 3; q++) {
            cs[s*3+q] = g_ps[o+q];
            ci[s*3+q] = g_pi[o+q];
        }
    }

    const float NEG = -__int_as_float(0x7f800000);
    int   wi[3];
#pragma unroll
    for (int pass = 0; pass < 3; pass++) {
        float bs = NEG; int bidx = 0x7fffffff; int bk = 0;
#pragma unroll
        for (int k = 0; k < NSPLIT * 3; k++) {
            bool better = (cs[k] > bs) || (cs[k] == bs && ci[k] < bidx);
            if (better) { bs = cs[k]; bidx = ci[k]; bk = k; }
        }
        wi[pass] = bidx;
        cs[bk] = NEG; ci[bk] = 0x7fffffff;
    }

    float ux = unknown[n*3], uy = unknown[n*3+1], uz = unknown[n*3+2];
    float d[3];
#pragma unroll
    for (int q = 0; q < 3; q++) {
        int ai = wi[q];
        float dx = ux - known[ai*3+0];
        float dy = uy - known[ai*3+1];
        float dz = uz - known[ai*3+2];
        d[q] = dx*dx + dy*dy + dz*dz;
    }
    float r0 = 1.f/(d[0]+1e-8f), r1 = 1.f/(d[1]+1e-8f), r2 = 1.f/(d[2]+1e-8f);
    float sm = 1.f/(r0+r1+r2);
    g_w[n*3+0] = r0*sm; g_w[n*3+1] = r1*sm; g_w[n*3+2] = r2*sm;
    g_i[n*3+0] = wi[0]; g_i[n*3+1] = wi[1]; g_i[n*3+2] = wi[2];
}

// ---------------- 2) fused SGEMM family (f32x2, R10-proven mainloop) ---------
// MODE 2: A = Asrc plain; no stats               (G = kf @ W1a^T)
// MODE 3: A = Asrc plain; epilogue += w-gather of Gsrc; BN stats (layer 1)
template <int K, int WS, int MODE>
__global__ __launch_bounds__(256, 2) void gemm_fused(
    const float* __restrict__ Asrc,
    const float* __restrict__ Gsrc,
    const float* __restrict__ W,
    float* __restrict__ Cdst)
{
    __shared__ float As[2][16][128];
    __shared__ float Bs[2][16][128];

    const int tid = threadIdx.x;
    const int tx = tid & 15;
    const int ty = tid >> 4;
    const int ar = tid >> 1;
    const int ks = (tid & 1) * 8;
    const int row0 = blockIdx.y * 128;
    const float* Wb = W + (size_t)blockIdx.x * 128 * WS;

    const int n = row0 + ar;

    auto loadA4 = [&](int k0) -> float4 {
        return *(const float4*)(Asrc + (size_t)n * K + k0);
    };

    unsigned long long acc2[8][4];
#pragma unroll
    for (int i = 0; i < 8; i++)
#pragma unroll
        for (int jp = 0; jp < 4; jp++) acc2[i][jp] = 0ULL;

    {
        float4 a0 = loadA4(ks);
        float4 a1 = loadA4(ks + 4);
        float4 q0 = *(const float4*)(Wb + (size_t)ar * WS + ks);
        float4 q1 = *(const float4*)(Wb + (size_t)ar * WS + ks + 4);
        As[0][ks+0][ar] = a0.x; As[0][ks+1][ar] = a0.y;
        As[0][ks+2][ar] = a0.z; As[0][ks+3][ar] = a0.w;
        As[0][ks+4][ar] = a1.x; As[0][ks+5][ar] = a1.y;
        As[0][ks+6][ar] = a1.z; As[0][ks+7][ar] = a1.w;
        Bs[0][ks+0][ar] = q0.x; Bs[0][ks+1][ar] = q0.y;
        Bs[0][ks+2][ar] = q0.z; Bs[0][ks+3][ar] = q0.w;
        Bs[0][ks+4][ar] = q1.x; Bs[0][ks+5][ar] = q1.y;
        Bs[0][ks+6][ar] = q1.z; Bs[0][ks+7][ar] = q1.w;
    }
    __syncthreads();

    const uint32_t bs_base = (uint32_t)__cvta_generic_to_shared(&Bs[0][0][0]);

    const int NK = K / 16;
#pragma unroll 1
    for (int kt = 0; kt < NK; kt++) {
        const int buf = kt & 1;
        float4 na0, na1, nq0, nq1;
        if (kt + 1 < NK) {
            const int kb = (kt + 1) * 16;
            na0 = loadA4(kb + ks);
            na1 = loadA4(kb + ks + 4);
            nq0 = *(const float4*)(Wb + (size_t)ar * WS + kb + ks);
            nq1 = *(const float4*)(Wb + (size_t)ar * WS + kb + ks + 4);
        }
        const uint32_t bbase = bs_base + ((uint32_t)buf * 2048 + (uint32_t)tx * 4) * 4;
#pragma unroll
        for (int k = 0; k < 16; k++) {
            float4 a0 = *(const float4*)&As[buf][k][ty * 8];
            float4 a1 = *(const float4*)&As[buf][k][ty * 8 + 4];
            unsigned long long b2[4];
            uint32_t baddr = bbase + (uint32_t)k * 512;
            asm volatile("ld.shared.v2.b64 {%0,%1}, [%2];"
                         : "=l"(b2[0]), "=l"(b2[1]) : "r"(baddr));
            asm volatile("ld.shared.v2.b64 {%0,%1}, [%2];"
                         : "=l"(b2[2]), "=l"(b2[3]) : "r"(baddr + 256));
            float ra[8] = {a0.x, a0.y, a0.z, a0.w, a1.x, a1.y, a1.z, a1.w};
#pragma unroll
            for (int i = 0; i < 8; i++) {
                unsigned long long ad;
                asm("mov.b64 %0, {%1, %1};" : "=l"(ad) : "f"(ra[i]));
                asm("fma.rn.f32x2 %0, %1, %2, %0;" : "+l"(acc2[i][0]) : "l"(ad), "l"(b2[0]));
                asm("fma.rn.f32x2 %0, %1, %2, %0;" : "+l"(acc2[i][1]) : "l"(ad), "l"(b2[1]));
                asm("fma.rn.f32x2 %0, %1, %2, %0;" : "+l"(acc2[i][2]) : "l"(ad), "l"(b2[2]));
                asm("fma.rn.f32x2 %0, %1, %2, %0;" : "+l"(acc2[i][3]) : "l"(ad), "l"(b2[3]));
            }
        }
        if (kt + 1 < NK) {
            const int nb = buf ^ 1;
            As[nb][ks+0][ar] = na0.x; As[nb][ks+1][ar] = na0.y;
            As[nb][ks+2][ar] = na0.z; As[nb][ks+3][ar] = na0.w;
            As[nb][ks+4][ar] = na1.x; As[nb][ks+5][ar] = na1.y;
            As[nb][ks+6][ar] = na1.z; As[nb][ks+7][ar] = na1.w;
            Bs[nb][ks+0][ar] = nq0.x; Bs[nb][ks+1][ar] = nq0.y;
            Bs[nb][ks+2][ar] = nq0.z; Bs[nb][ks+3][ar] = nq0.w;
            Bs[nb][ks+4][ar] = nq1.x; Bs[nb][ks+5][ar] = nq1.y;
            Bs[nb][ks+6][ar] = nq1.z; Bs[nb][ks+7][ar] = nq1.w;
        }
        __syncthreads();
    }

    float acc[8][8];
#pragma unroll
    for (int i = 0; i < 8; i++)
#pragma unroll
        for (int jp = 0; jp < 4; jp++) {
            asm("mov.b64 {%0, %1}, %2;"
                : "=f"(acc[i][2*jp+0]), "=f"(acc[i][2*jp+1]) : "l"(acc2[i][jp]));
        }

    if (MODE == 3) {
        const int colbase = blockIdx.x * 128;
#pragma unroll 1
        for (int i = 0; i < 8; i++) {
            int nn = row0 + ty * 8 + i;
            float w0 = g_w[nn*3+0], w1 = g_w[nn*3+1], w2 = g_w[nn*3+2];
            int   j0 = g_i[nn*3+0], j1 = g_i[nn*3+1], j2 = g_i[nn*3+2];
            const float* G0 = Gsrc + (size_t)j0 * COUT + colbase;
            const float* G1 = Gsrc + (size_t)j1 * COUT + colbase;
            const float* G2 = Gsrc + (size_t)j2 * COUT + colbase;
            float4 p0 = *(const float4*)(G0 + tx*4);
            float4 p1 = *(const float4*)(G1 + tx*4);
            float4 p2 = *(const float4*)(G2 + tx*4);
            acc[i][0] += w0*p0.x + w1*p1.x + w2*p2.x;
            acc[i][1] += w0*p0.y + w1*p1.y + w2*p2.y;
            acc[i][2] += w0*p0.z + w1*p1.z + w2*p2.z;
            acc[i][3] += w0*p0.w + w1*p1.w + w2*p2.w;
            float4 r0v = *(const float4*)(G0 + 64 + tx*4);
            float4 r1v = *(const float4*)(G1 + 64 + tx*4);
            float4 r2v = *(const float4*)(G2 + 64 + tx*4);
            acc[i][4] += w0*r0v.x + w1*r1v.x + w2*r2v.x;
            acc[i][5] += w0*r0v.y + w1*r1v.y + w2*r2v.y;
            acc[i][6] += w0*r0v.z + w1*r1v.z + w2*r2v.z;
            acc[i][7] += w0*r0v.w + w1*r1v.w + w2*r2v.w;
        }
    }

    float* Cb = Cdst + (size_t)(row0 + ty * 8) * COUT + blockIdx.x * 128;
#pragma unroll
    for (int i = 0; i < 8; i++) {
        *(float4*)(Cb + (size_t)i * COUT + tx * 4)      = make_float4(acc[i][0], acc[i][1], acc[i][2], acc[i][3]);
        *(float4*)(Cb + (size_t)i * COUT + 64 + tx * 4) = make_float4(acc[i][4], acc[i][5], acc[i][6], acc[i][7]);
    }

    if (MODE == 3) {
        float cs[8], cq[8];
#pragma unroll
        for (int j = 0; j < 8; j++) { cs[j] = 0.f; cq[j] = 0.f; }
#pragma unroll
        for (int i = 0; i < 8; i++)
#pragma unroll
            for (int j = 0; j < 8; j++) {
                float v = acc[i][j];
                cs[j] += v;
                cq[j] = fmaf(v, v, cq[j]);
            }
        float (*ps)[128] = reinterpret_cast<float(*)[128]>(&As[0][0][0]);
        float (*pq)[128] = reinterpret_cast<float(*)[128]>(&Bs[0][0][0]);
        __syncthreads();
#pragma unroll
        for (int j = 0; j < 4; j++) {
            ps[ty][tx*4 + j]      = cs[j];
            pq[ty][tx*4 + j]      = cq[j];
            ps[ty][64 + tx*4 + j] = cs[4 + j];
            pq[ty][64 + tx*4 + j] = cq[4 + j];
        }
        __syncthreads();
        if (tid < 128) {
            float sv = 0.f, qv = 0.f;
#pragma unroll
            for (int t16 = 0; t16 < 16; t16++) { sv += ps[t16][tid]; qv += pq[t16][tid]; }
            int c = blockIdx.x * 128 + tid;
            g_psum[(size_t)c * PARTS + blockIdx.y] = sv;
            g_psq [(size_t)c * PARTS + blockIdx.y] = qv;
        }
    }
}

// ---------------- 2b) gemm2 via wmma tf32 (3x split) -------------------------
// C[m,o] = sum_k relu(bn(A[m,k])) * W[o,k], K=256.
// CTA 128x128, 8 warps (2 along M x 4 along N), warp tile 64x32,
// wmma m16n16k8 tf32: per warp 4x2 accum frags, 3-term split per k8 slice.
__global__ __launch_bounds__(256, 2) void gemm2_wmma(
    const float* __restrict__ Asrc,   // H1 [N][256]
    const float* __restrict__ W,      // W2 [256][256]
    float* __restrict__ Cdst)
{
    __shared__ float Ahi[2][8][128], Alo[2][8][128];  // [buf][k][m]  (col-major A)
    __shared__ float Bhi[2][8][128], Blo[2][8][128];  // [buf][k][n]  (row-major B)
    __shared__ float ssc[256], ssh[256];

    const int tid  = threadIdx.x;
    const int warp = tid >> 5;
    const int wm   = warp & 1;        // 2 warps along M (64 rows each)
    const int wn   = warp >> 1;       // 4 warps along N (32 cols each)
    const int row0 = blockIdx.y * 128;
    const int col0 = blockIdx.x * 128;

    ssc[tid] = g_scale[tid]; ssh[tid] = g_shift[tid];

    const int ar = tid >> 1;          // 0..127
    const int kq = (tid & 1) * 4;     // 0 or 4
    __syncthreads();

    auto stageA = [&](int buf, int k0) {
        float4 v = *(const float4*)(Asrc + (size_t)(row0 + ar) * COUT + k0 + kq);
        v.x = fmaxf(fmaf(v.x, ssc[k0+kq+0], ssh[k0+kq+0]), 0.f);
        v.y = fmaxf(fmaf(v.y, ssc[k0+kq+1], ssh[k0+kq+1]), 0.f);
        v.z = fmaxf(fmaf(v.z, ssc[k0+kq+2], ssh[k0+kq+2]), 0.f);
        v.w = fmaxf(fmaf(v.w, ssc[k0+kq+3], ssh[k0+kq+3]), 0.f);
        float hx = tf32_rnd(v.x), hy = tf32_rnd(v.y), hz = tf32_rnd(v.z), hw = tf32_rnd(v.w);
        Ahi[buf][kq+0][ar] = hx; Alo[buf][kq+0][ar] = tf32_rnd(v.x - hx);
        Ahi[buf][kq+1][ar] = hy; Alo[buf][kq+1][ar] = tf32_rnd(v.y - hy);
        Ahi[buf][kq+2][ar] = hz; Alo[buf][kq+2][ar] = tf32_rnd(v.z - hz);
        Ahi[buf][kq+3][ar] = hw; Alo[buf][kq+3][ar] = tf32_rnd(v.w - hw);
    };
    auto stageB = [&](int buf, int k0) {
        float4 v = *(const float4*)(W + (size_t)(col0 + ar) * COUT + k0 + kq);
        float hx = tf32_rnd(v.x), hy = tf32_rnd(v.y), hz = tf32_rnd(v.z), hw = tf32_rnd(v.w);
        Bhi[buf][kq+0][ar] = hx; Blo[buf][kq+0][ar] = tf32_rnd(v.x - hx);
        Bhi[buf][kq+1][ar] = hy; Blo[buf][kq+1][ar] = tf32_rnd(v.y - hy);
        Bhi[buf][kq+2][ar] = hz; Blo[buf][kq+2][ar] = tf32_rnd(v.z - hz);
        Bhi[buf][kq+3][ar] = hw; Blo[buf][kq+3][ar] = tf32_rnd(v.w - hw);
    };

    wmma::fragment<wmma::accumulator, 16, 16, 8, float> cf[4][2];
#pragma unroll
    for (int mt = 0; mt < 4; mt++)
#pragma unroll
        for (int nt = 0; nt < 2; nt++) wmma::fill_fragment(cf[mt][nt], 0.f);

    stageA(0, 0);
    stageB(0, 0);
    __syncthreads();

    const int NSL = COUT / 8;         // 32 k-slices
#pragma unroll 1
    for (int sl = 0; sl < NSL; sl++) {
        const int buf = sl & 1;
        if (sl + 1 < NSL) {
            stageA(buf ^ 1, (sl + 1) * 8);
            stageB(buf ^ 1, (sl + 1) * 8);
        }

        wmma::fragment<wmma::matrix_b, 16, 16, 8, wmma::precision::tf32, wmma::row_major> bh[2], bl[2];
#pragma unroll
        for (int nt = 0; nt < 2; nt++) {
            wmma::load_matrix_sync(bh[nt], &Bhi[buf][0][wn * 32 + nt * 16], 128);
            wmma::load_matrix_sync(bl[nt], &Blo[buf][0][wn * 32 + nt * 16], 128);
        }
#pragma unroll
        for (int mt = 0; mt < 4; mt++) {
            wmma::fragment<wmma::matrix_a, 16, 16, 8, wmma::precision::tf32, wmma::col_major> ah, al;
            wmma::load_matrix_sync(ah, &Ahi[buf][0][wm * 64 + mt * 16], 128);
            wmma::load_matrix_sync(al, &Alo[buf][0][wm * 64 + mt * 16], 128);
#pragma unroll
            for (int nt = 0; nt < 2; nt++) {
                wmma::mma_sync(cf[mt][nt], ah, bh[nt], cf[mt][nt]);
                wmma::mma_sync(cf[mt][nt], ah, bl[nt], cf[mt][nt]);
                wmma::mma_sync(cf[mt][nt], al, bh[nt], cf[mt][nt]);
            }
        }
        __syncthreads();
    }

    // store C directly to global
#pragma unroll
    for (int mt = 0; mt < 4; mt++)
#pragma unroll
        for (int nt = 0; nt < 2; nt++) {
            float* dst = Cdst + (size_t)(row0 + wm * 64 + mt * 16) * COUT
                              + col0 + wn * 32 + nt * 16;
            wmma::store_matrix_sync(dst, cf[mt][nt], COUT, wmma::mem_row_major);
        }
}

// ---------------- 2c) column stats for H2 (layer-2 BN) -----------------------
__global__ void col_stats2(const float* __restrict__ H, int N)
{
    int c = threadIdx.x;                        // 256 cols
    int rows = N / gridDim.x;
    int r0 = blockIdx.x * rows;
    float s = 0.f, sq = 0.f;
    for (int r = r0; r < r0 + rows; r++) {
        float v = H[(size_t)r * COUT + c];
        s += v;
        sq = fmaf(v, v, sq);
    }
    g_psum[(size_t)c * PARTS + blockIdx.x] = s;
    g_psq [(size_t)c * PARTS + blockIdx.x] = sq;
}

// ---------------- 3) parallel BN finalize (one block per column) ------------
__global__ __launch_bounds__(256) void finalize_par(
    const float* __restrict__ gamma,
    const float* __restrict__ beta,
    int N, int nblk)
{
    __shared__ double sd[256], sq[256];
    const int c = blockIdx.x;
    const int t = threadIdx.x;
    double v = 0.0, q = 0.0;
    for (int b = t; b < nblk; b += 256) {
        v += (double)g_psum[(size_t)c * PARTS + b];
        q += (double)g_psq [(size_t)c * PARTS + b];
    }
    sd[t] = v; sq[t] = q;
    __syncthreads();
    for (int off = 128; off > 0; off >>= 1) {
        if (t < off) { sd[t] += sd[t + off]; sq[t] += sq[t + off]; }
        __syncthreads();
    }
    if (t == 0) {
        double mean = sd[0] / (double)N;
        double var  = sq[0] / (double)N - mean * mean;
        float  sc   = gamma[c] * rsqrtf((float)var + 1e-5f);
        g_scale[c] = sc;
        g_shift[c] = beta[c] - (float)mean * sc;
    }
}

// ---------------- 4) final BN apply + ReLU (vectorized) ----------------------
__global__ void bn_relu_out4(const float4* __restrict__ H, float4* __restrict__ out, int total4)
{
    int t = blockIdx.x * blockDim.x + threadIdx.x;
    if (t < total4) {
        int c = (t & 63) * 4;
        float4 v = H[t];
        v.x = fmaxf(fmaf(v.x, g_scale[c+0], g_shift[c+0]), 0.f);
        v.y = fmaxf(fmaf(v.y, g_scale[c+1], g_shift[c+1]), 0.f);
        v.z = fmaxf(fmaf(v.z, g_scale[c+2], g_shift[c+2]), 0.f);
        v.w = fmaxf(fmaf(v.w, g_scale[c+3], g_shift[c+3]), 0.f);
        out[t] = v;
    }
}

// ---------------- launch -----------------------------------------------------
extern "C" void kernel_launch(void* const* d_in, const int* in_sizes, int n_in,
                              void* d_out, int out_size)
{
    const float* unknown = (const float*)d_in[0];
    const int*   ub_cnt  = (const int*)  d_in[1];
    const float* known   = (const float*)d_in[2];
    const int*   kb_cnt  = (const int*)  d_in[3];
    const float* uf      = (const float*)d_in[4];
    const float* kf      = (const float*)d_in[5];
    const float* W1      = (const float*)d_in[6];
    const float* g1      = (const float*)d_in[7];
    const float* b1      = (const float*)d_in[8];
    const float* W2      = (const float*)d_in[9];
    const float* g2      = (const float*)d_in[10];
    const float* b2      = (const float*)d_in[11];
    float* out = (float*)d_out;

    int N  = in_sizes[0] / 3;
    int Mk = in_sizes[2] / 3;
    int B  = in_sizes[1];
    int nblk  = N  / 128;
    int nblkG = Mk / 128;
    int total4 = (int)(((long)N * COUT) / 4);

    float* Hp = nullptr; float* H2p = nullptr; float* Gp = nullptr;
    cudaGetSymbolAddress((void**)&Hp,  g_H);
    cudaGetSymbolAddress((void**)&H2p, g_H2);
    cudaGetSymbolAddress((void**)&Gp,  g_G);

    three_nn_part<<<dim3((N + 511) / 512, NSPLIT), 256>>>(unknown, ub_cnt, known, kb_cnt, N, B);
    three_nn_merge<<<(N + 255) / 256, 256>>>(unknown, known, N);

    // G = kf @ W1a^T
    gemm_fused<256, CIN, 2><<<dim3(2, nblkG), 256>>>(kf, nullptr, W1, Gp);

    // H1 = uf @ W1b^T + weighted gather of G; emits BN-stat partials
    gemm_fused<128, CIN, 3><<<dim3(2, nblk), 256>>>(uf, Gp, W1 + C2, Hp);
    finalize_par<<<COUT, 256>>>(g1, b1, N, nblk);

    // H2 = relu(bn(H1)) @ W2^T  (wmma tf32 3x)
    gemm2_wmma<<<dim3(2, nblk), 256>>>(Hp, W2, H2p);
    col_stats2<<<STATB2, COUT>>>(H2p, N);
    finalize_par<<<COUT, 256>>>(g2, b2, N, STATB2);

    bn_relu_out4<<<(total4 + 255) / 256, 256>>>((const float4*)H2p, (float4*)out, total4);
}